// round 1
// baseline (speedup 1.0000x reference)
#include <cuda_runtime.h>
#include <cstdint>

// Problem constants
#define NB    1024   // batch
#define BT    256    // block_size (seq len)
#define CE    384    // n_embed
#define HS    64     // head_size

// Scratch for q, k, v projections (device globals: no allocation allowed)
__device__ float g_q[(size_t)NB * BT * HS];
__device__ float g_k[(size_t)NB * BT * HS];
__device__ float g_v[(size_t)NB * BT * HS];

// ---------------------------------------------------------------------------
// Kernel 1: fused QKV projection.
// x: [NB*BT, CE] row-major. Wq/Wk/Wv: [CE, HS] row-major ([in, out]).
// Each block: 64 rows x 192 outputs (all of q,k,v). 256 threads.
// Thread (ty, tx): rows 4*ty..4*ty+3, cols 4*tx..4*tx+3 of each of the 3 outputs.
// k-chunked (BK=32): x tile stored TRANSPOSED in smem for broadcast float4 reads.
// ---------------------------------------------------------------------------
__global__ __launch_bounds__(256) void qkv_proj_kernel(
    const float* __restrict__ x,
    const float* __restrict__ Wq,
    const float* __restrict__ Wk,
    const float* __restrict__ Wv)
{
    __shared__ float xst[32 * 68];       // [kk][row], padded stride 68
    __shared__ float ws[3 * 32 * 64];    // [w][kk][col]

    const int tid = threadIdx.x;
    const int tx = tid & 15;
    const int ty = tid >> 4;
    const int rowBase = blockIdx.x * 64;

    float acc[3][4][4];
    #pragma unroll
    for (int w = 0; w < 3; ++w)
        #pragma unroll
        for (int i = 0; i < 4; ++i)
            #pragma unroll
            for (int j = 0; j < 4; ++j)
                acc[w][i][j] = 0.0f;

    for (int k0 = 0; k0 < CE; k0 += 32) {
        // Load x tile [64 rows x 32 k] transposed into xst[kk][row]
        for (int i = tid; i < 512; i += 256) {          // 512 float4 = 64*32 floats
            int r  = i >> 3;                            // 8 float4 per row
            int k4 = i & 7;
            float4 v = *(const float4*)(x + (size_t)(rowBase + r) * CE + k0 + k4 * 4);
            xst[(k4 * 4 + 0) * 68 + r] = v.x;
            xst[(k4 * 4 + 1) * 68 + r] = v.y;
            xst[(k4 * 4 + 2) * 68 + r] = v.z;
            xst[(k4 * 4 + 3) * 68 + r] = v.w;
        }
        // Load W chunks [32 x 64] for all three matrices
        for (int i = tid; i < 1536; i += 256) {         // 1536 float4 = 3*32*64 floats
            int w   = i >> 9;
            int rem = i & 511;
            int r   = rem >> 4;
            int c4  = rem & 15;
            const float* W = (w == 0) ? Wq : (w == 1) ? Wk : Wv;
            *(float4*)&ws[w * 2048 + r * 64 + c4 * 4] =
                *(const float4*)(W + (size_t)(k0 + r) * HS + c4 * 4);
        }
        __syncthreads();

        #pragma unroll 4
        for (int kk = 0; kk < 32; ++kk) {
            float4 a  = *(const float4*)&xst[kk * 68 + ty * 4];
            float4 b0 = *(const float4*)&ws[         kk * 64 + tx * 4];
            float4 b1 = *(const float4*)&ws[2048 +   kk * 64 + tx * 4];
            float4 b2 = *(const float4*)&ws[4096 +   kk * 64 + tx * 4];
            float av[4] = {a.x, a.y, a.z, a.w};
            float bv[3][4] = {{b0.x, b0.y, b0.z, b0.w},
                              {b1.x, b1.y, b1.z, b1.w},
                              {b2.x, b2.y, b2.z, b2.w}};
            #pragma unroll
            for (int w = 0; w < 3; ++w)
                #pragma unroll
                for (int i = 0; i < 4; ++i)
                    #pragma unroll
                    for (int j = 0; j < 4; ++j)
                        acc[w][i][j] += av[i] * bv[w][j];
        }
        __syncthreads();
    }

    // Store q, k, v
    #pragma unroll
    for (int w = 0; w < 3; ++w) {
        float* dst = (w == 0) ? g_q : (w == 1) ? g_k : g_v;
        #pragma unroll
        for (int i = 0; i < 4; ++i) {
            size_t row = (size_t)rowBase + ty * 4 + i;
            float4 r4 = make_float4(acc[w][i][0], acc[w][i][1], acc[w][i][2], acc[w][i][3]);
            *(float4*)(dst + row * HS + tx * 4) = r4;
        }
    }
}

// ---------------------------------------------------------------------------
// Kernel 2: fused causal flash attention over q,k,v (fp32).
// Grid: (4 query tiles, 1024 batches). Block: 256 threads.
// Thread (ty, tx): query rows 4*ty..+3; for scores key cols 4*tx..+3,
// for output head-dims 4*tx..+3. Online softmax with running (m, l).
// smem: qs row-major, kst transposed (float4 b-loads), vs row-major, ps row-major.
// ---------------------------------------------------------------------------
#define ATT_STRIDE 68
#define ATT_SMEM_BYTES (4 * 64 * ATT_STRIDE * 4)   // 69632 B

__global__ __launch_bounds__(256) void attn_kernel(float* __restrict__ out)
{
    extern __shared__ float sm[];
    float* qs  = sm;                       // [row][h]   stride 68
    float* kst = sm + 64 * ATT_STRIDE;     // [h][key]   stride 68
    float* vs  = sm + 2 * 64 * ATT_STRIDE; // [key][h]   stride 68
    float* ps  = sm + 3 * 64 * ATT_STRIDE; // [row][key] stride 68

    const int b   = blockIdx.y;
    const int qt  = blockIdx.x;
    const int tid = threadIdx.x;
    const int tx  = tid & 15;
    const int ty  = tid >> 4;
    const float scale = 0.05103103630798288f;   // 384^-0.5

    // Load q tile (row-major, float4)
    const float* qb = g_q + ((size_t)b * BT + qt * 64) * HS;
    for (int i = tid; i < 1024; i += 256) {   // 1024 float4 = 64*64
        int r  = i >> 4;
        int c4 = i & 15;
        float4 v = *(const float4*)(qb + r * HS + c4 * 4);
        *(float4*)&qs[r * ATT_STRIDE + c4 * 4] = v;
    }

    float m[4], l[4], o[4][4];
    #pragma unroll
    for (int i = 0; i < 4; ++i) {
        m[i] = -1e30f;
        l[i] = 0.0f;
        #pragma unroll
        for (int j = 0; j < 4; ++j) o[i][j] = 0.0f;
    }

    for (int st = 0; st <= qt; ++st) {
        const float* kb = g_k + ((size_t)b * BT + st * 64) * HS;
        const float* vb = g_v + ((size_t)b * BT + st * 64) * HS;
        // k transposed: kst[h][key]; v row-major
        for (int i = tid; i < 1024; i += 256) {
            int r  = i >> 4;
            int c4 = i & 15;
            float4 kv = *(const float4*)(kb + r * HS + c4 * 4);
            kst[(c4 * 4 + 0) * ATT_STRIDE + r] = kv.x;
            kst[(c4 * 4 + 1) * ATT_STRIDE + r] = kv.y;
            kst[(c4 * 4 + 2) * ATT_STRIDE + r] = kv.z;
            kst[(c4 * 4 + 3) * ATT_STRIDE + r] = kv.w;
            float4 vv = *(const float4*)(vb + r * HS + c4 * 4);
            *(float4*)&vs[r * ATT_STRIDE + c4 * 4] = vv;
        }
        __syncthreads();

        // Scores: sc[i][j] = sum_h q[4ty+i][h] * k[4tx+j][h]
        float sc[4][4];
        #pragma unroll
        for (int i = 0; i < 4; ++i)
            #pragma unroll
            for (int j = 0; j < 4; ++j) sc[i][j] = 0.0f;

        #pragma unroll 8
        for (int h = 0; h < 64; ++h) {
            float a0 = qs[(ty * 4 + 0) * ATT_STRIDE + h];
            float a1 = qs[(ty * 4 + 1) * ATT_STRIDE + h];
            float a2 = qs[(ty * 4 + 2) * ATT_STRIDE + h];
            float a3 = qs[(ty * 4 + 3) * ATT_STRIDE + h];
            float4 bb = *(const float4*)&kst[h * ATT_STRIDE + tx * 4];
            sc[0][0] += a0 * bb.x; sc[0][1] += a0 * bb.y; sc[0][2] += a0 * bb.z; sc[0][3] += a0 * bb.w;
            sc[1][0] += a1 * bb.x; sc[1][1] += a1 * bb.y; sc[1][2] += a1 * bb.z; sc[1][3] += a1 * bb.w;
            sc[2][0] += a2 * bb.x; sc[2][1] += a2 * bb.y; sc[2][2] += a2 * bb.z; sc[2][3] += a2 * bb.w;
            sc[3][0] += a3 * bb.x; sc[3][1] += a3 * bb.y; sc[3][2] += a3 * bb.z; sc[3][3] += a3 * bb.w;
        }

        // Scale + causal mask
        const int qi0 = qt * 64 + ty * 4;
        const int kj0 = st * 64 + tx * 4;
        #pragma unroll
        for (int i = 0; i < 4; ++i)
            #pragma unroll
            for (int j = 0; j < 4; ++j) {
                float v = sc[i][j] * scale;
                if (kj0 + j > qi0 + i) v = -1e30f;
                sc[i][j] = v;
            }

        // Online softmax update (per query row, reduced over the 16 tx lanes)
        #pragma unroll
        for (int i = 0; i < 4; ++i) {
            float rmax = fmaxf(fmaxf(sc[i][0], sc[i][1]), fmaxf(sc[i][2], sc[i][3]));
            #pragma unroll
            for (int off = 8; off > 0; off >>= 1)
                rmax = fmaxf(rmax, __shfl_xor_sync(0xffffffffu, rmax, off, 16));
            float mnew  = fmaxf(m[i], rmax);
            float alpha = __expf(m[i] - mnew);
            float rsum  = 0.0f;
            #pragma unroll
            for (int j = 0; j < 4; ++j) {
                float p = __expf(sc[i][j] - mnew);
                ps[(ty * 4 + i) * ATT_STRIDE + tx * 4 + j] = p;
                rsum += p;
            }
            #pragma unroll
            for (int off = 8; off > 0; off >>= 1)
                rsum += __shfl_xor_sync(0xffffffffu, rsum, off, 16);
            l[i] = l[i] * alpha + rsum;
            m[i] = mnew;
            #pragma unroll
            for (int j = 0; j < 4; ++j) o[i][j] *= alpha;
        }
        __syncthreads();

        // PV: o[i][j] += sum_s ps[4ty+i][s] * vs[s][4tx+j]
        #pragma unroll 8
        for (int s2 = 0; s2 < 64; ++s2) {
            float a0 = ps[(ty * 4 + 0) * ATT_STRIDE + s2];
            float a1 = ps[(ty * 4 + 1) * ATT_STRIDE + s2];
            float a2 = ps[(ty * 4 + 2) * ATT_STRIDE + s2];
            float a3 = ps[(ty * 4 + 3) * ATT_STRIDE + s2];
            float4 bb = *(const float4*)&vs[s2 * ATT_STRIDE + tx * 4];
            o[0][0] += a0 * bb.x; o[0][1] += a0 * bb.y; o[0][2] += a0 * bb.z; o[0][3] += a0 * bb.w;
            o[1][0] += a1 * bb.x; o[1][1] += a1 * bb.y; o[1][2] += a1 * bb.z; o[1][3] += a1 * bb.w;
            o[2][0] += a2 * bb.x; o[2][1] += a2 * bb.y; o[2][2] += a2 * bb.z; o[2][3] += a2 * bb.w;
            o[3][0] += a3 * bb.x; o[3][1] += a3 * bb.y; o[3][2] += a3 * bb.z; o[3][3] += a3 * bb.w;
        }
        __syncthreads();
    }

    // Epilogue: normalize and store
    float* ob = out + ((size_t)b * BT + qt * 64) * HS;
    #pragma unroll
    for (int i = 0; i < 4; ++i) {
        float inv = 1.0f / l[i];
        float4 r4 = make_float4(o[i][0] * inv, o[i][1] * inv, o[i][2] * inv, o[i][3] * inv);
        *(float4*)(ob + (ty * 4 + i) * HS + tx * 4) = r4;
    }
}

// ---------------------------------------------------------------------------
// Launch
// ---------------------------------------------------------------------------
extern "C" void kernel_launch(void* const* d_in, const int* in_sizes, int n_in,
                              void* d_out, int out_size)
{
    (void)in_sizes; (void)n_in; (void)out_size;
    const float* x  = (const float*)d_in[0];
    const float* Wq = (const float*)d_in[1];
    const float* Wk = (const float*)d_in[2];
    const float* Wv = (const float*)d_in[3];
    float* out = (float*)d_out;

    cudaFuncSetAttribute(attn_kernel,
                         cudaFuncAttributeMaxDynamicSharedMemorySize,
                         ATT_SMEM_BYTES);

    // QKV projection: 262144 rows / 64 per block = 4096 blocks
    qkv_proj_kernel<<<4096, 256>>>(x, Wq, Wk, Wv);

    // Attention: 4 query tiles x 1024 batches
    attn_kernel<<<dim3(4, NB), 256, ATT_SMEM_BYTES>>>(out);
}

// round 4
// speedup vs baseline: 1.1187x; 1.1187x over previous
#include <cuda_runtime.h>
#include <cuda_bf16.h>
#include <mma.h>
#include <cstdint>

using namespace nvcuda;

// Problem constants
#define NB    1024   // batch
#define BT    256    // block_size (seq len)
#define CE    384    // n_embed
#define HS    64     // head_size

// Scratch (device globals: no allocation allowed)
__device__ float g_q[(size_t)NB * BT * HS];
__device__ float g_k[(size_t)NB * BT * HS];
__device__ float g_v[(size_t)NB * BT * HS];
// Combined bf16 hi/lo weights: [CE][192] where cols = [Wq | Wk | Wv]
__device__ __nv_bfloat16 g_whc[CE * 192];
__device__ __nv_bfloat16 g_wlc[CE * 192];

// ---------------------------------------------------------------------------
// Kernel 0: convert W (q,k,v) into combined bf16 hi/lo [CE][192].
// ---------------------------------------------------------------------------
__global__ void wconv_kernel(const float* __restrict__ Wq,
                             const float* __restrict__ Wk,
                             const float* __restrict__ Wv) {
    int i = blockIdx.x * blockDim.x + threadIdx.x;
    if (i >= 3 * CE * HS) return;
    int w = i / (CE * HS);
    int r = i % (CE * HS);
    int k = r / HS;
    int n = r % HS;
    const float* W = (w == 0) ? Wq : (w == 1) ? Wk : Wv;
    float v = W[k * HS + n];
    __nv_bfloat16 h = __float2bfloat16(v);
    __nv_bfloat16 l = __float2bfloat16(v - __bfloat162float(h));
    g_whc[k * 192 + w * 64 + n] = h;
    g_wlc[k * 192 + w * 64 + n] = l;
}

// ---------------------------------------------------------------------------
// Kernel 1: QKV projection on tensor cores (WMMA bf16, split hi/lo, 3 MMAs).
// CTA tile: 128 rows x 192 cols (q|k|v). 384 threads = 12 warps (4m x 3n).
// Warp tile: 32 x 64 -> 2x4 wmma 16x16x16 fragments.
// K chunked at 32 (12 chunks over CE=384).
// hi/lo tiles live in ONE shared array each (defined relative offsets).
// ---------------------------------------------------------------------------
#define AST 40                     // A smem stride (elements)
#define A_LO (128 * AST)           // lo offset within a_s (elements)
#define B_LO (32 * 192)            // lo offset within b_s (elements)

__global__ __launch_bounds__(384) void qkv_proj_wmma(const float* __restrict__ x)
{
    __shared__ __align__(32) __nv_bfloat16 a_s[2 * 128 * AST];
    __shared__ __align__(32) __nv_bfloat16 b_s[2 * 32 * 192];

    const int tid = threadIdx.x;
    const int wrp = tid >> 5;
    const int wym = wrp / 3;         // 0..3 (m)
    const int wxn = wrp % 3;         // 0..2 (n -> q/k/v)
    const size_t rowBase = (size_t)blockIdx.x * 128;

    wmma::fragment<wmma::accumulator, 16, 16, 16, float> acc[2][4];
    #pragma unroll
    for (int i = 0; i < 2; ++i)
        #pragma unroll
        for (int j = 0; j < 4; ++j)
            wmma::fill_fragment(acc[i][j], 0.0f);

    for (int kc = 0; kc < 12; ++kc) {
        // --- load & convert x tile: 128 rows x 32 k (fp32 -> bf16 hi/lo) ---
        #pragma unroll
        for (int i = tid; i < 1024; i += 384) {     // 1024 float4 = 128*32 floats
            int r  = i >> 3;
            int c4 = i & 7;
            float4 v = *(const float4*)(x + (rowBase + r) * CE + kc * 32 + c4 * 4);
            float hx = __bfloat162float(__float2bfloat16(v.x));
            float hy = __bfloat162float(__float2bfloat16(v.y));
            float hz = __bfloat162float(__float2bfloat16(v.z));
            float hw = __bfloat162float(__float2bfloat16(v.w));
            __nv_bfloat162 h01 = __floats2bfloat162_rn(v.x, v.y);
            __nv_bfloat162 h23 = __floats2bfloat162_rn(v.z, v.w);
            __nv_bfloat162 l01 = __floats2bfloat162_rn(v.x - hx, v.y - hy);
            __nv_bfloat162 l23 = __floats2bfloat162_rn(v.z - hz, v.w - hw);
            __nv_bfloat162* ph = (__nv_bfloat162*)&a_s[r * AST + c4 * 4];
            __nv_bfloat162* pl = (__nv_bfloat162*)&a_s[A_LO + r * AST + c4 * 4];
            ph[0] = h01; ph[1] = h23;
            pl[0] = l01; pl[1] = l23;
        }
        // --- copy W chunk: 32 rows x 192 cols bf16, hi+lo (uint4 = 8 elems) ---
        #pragma unroll
        for (int i = tid; i < 768; i += 384) {      // 768 uint4 = 32*192 bf16
            int r = i / 24;
            int c = i % 24;
            size_t src = (size_t)(kc * 32 + r) * 192 + c * 8;
            *(uint4*)&b_s[r * 192 + c * 8]        = *(const uint4*)&g_whc[src];
            *(uint4*)&b_s[B_LO + r * 192 + c * 8] = *(const uint4*)&g_wlc[src];
        }
        __syncthreads();

        // --- MMAs: per warp 2(m) x 4(n) x 2(kstep) x 3(split terms) ---
        #pragma unroll
        for (int ks = 0; ks < 2; ++ks) {
            wmma::fragment<wmma::matrix_a, 16, 16, 16, __nv_bfloat16, wmma::row_major> ah[2], al[2];
            wmma::fragment<wmma::matrix_b, 16, 16, 16, __nv_bfloat16, wmma::row_major> bh[4], bl[4];
            #pragma unroll
            for (int i = 0; i < 2; ++i) {
                const __nv_bfloat16* pa = &a_s[(wym * 32 + i * 16) * AST + ks * 16];
                wmma::load_matrix_sync(ah[i], pa, AST);
                wmma::load_matrix_sync(al[i], pa + A_LO, AST);
            }
            #pragma unroll
            for (int j = 0; j < 4; ++j) {
                const __nv_bfloat16* pb = &b_s[(ks * 16) * 192 + wxn * 64 + j * 16];
                wmma::load_matrix_sync(bh[j], pb, 192);
                wmma::load_matrix_sync(bl[j], pb + B_LO, 192);
            }
            #pragma unroll
            for (int i = 0; i < 2; ++i)
                #pragma unroll
                for (int j = 0; j < 4; ++j) {
                    wmma::mma_sync(acc[i][j], ah[i], bh[j], acc[i][j]);
                    wmma::mma_sync(acc[i][j], ah[i], bl[j], acc[i][j]);
                    wmma::mma_sync(acc[i][j], al[i], bh[j], acc[i][j]);
                }
        }
        __syncthreads();
    }

    // --- epilogue: each warp's 64-col range is exactly one of q/k/v ---
    float* dst = (wxn == 0) ? g_q : (wxn == 1) ? g_k : g_v;
    #pragma unroll
    for (int i = 0; i < 2; ++i) {
        size_t row = rowBase + wym * 32 + i * 16;
        #pragma unroll
        for (int j = 0; j < 4; ++j)
            wmma::store_matrix_sync(dst + row * HS + j * 16, acc[i][j], HS,
                                    wmma::mem_row_major);
    }
}

// ---------------------------------------------------------------------------
// Kernel 2: fused causal flash attention over q,k,v (fp32). (unchanged)
// ---------------------------------------------------------------------------
#define ATT_STRIDE 68
#define ATT_SMEM_BYTES (4 * 64 * ATT_STRIDE * 4)   // 69632 B

__global__ __launch_bounds__(256) void attn_kernel(float* __restrict__ out)
{
    extern __shared__ float sm[];
    float* qs  = sm;                       // [row][h]   stride 68
    float* kst = sm + 64 * ATT_STRIDE;     // [h][key]   stride 68
    float* vs  = sm + 2 * 64 * ATT_STRIDE; // [key][h]   stride 68
    float* ps  = sm + 3 * 64 * ATT_STRIDE; // [row][key] stride 68

    const int b   = blockIdx.y;
    const int qt  = blockIdx.x;
    const int tid = threadIdx.x;
    const int tx  = tid & 15;
    const int ty  = tid >> 4;
    const float scale = 0.05103103630798288f;   // 384^-0.5

    const float* qb = g_q + ((size_t)b * BT + qt * 64) * HS;
    for (int i = tid; i < 1024; i += 256) {
        int r  = i >> 4;
        int c4 = i & 15;
        float4 v = *(const float4*)(qb + r * HS + c4 * 4);
        *(float4*)&qs[r * ATT_STRIDE + c4 * 4] = v;
    }

    float m[4], l[4], o[4][4];
    #pragma unroll
    for (int i = 0; i < 4; ++i) {
        m[i] = -1e30f;
        l[i] = 0.0f;
        #pragma unroll
        for (int j = 0; j < 4; ++j) o[i][j] = 0.0f;
    }

    for (int st = 0; st <= qt; ++st) {
        const float* kb = g_k + ((size_t)b * BT + st * 64) * HS;
        const float* vb = g_v + ((size_t)b * BT + st * 64) * HS;
        for (int i = tid; i < 1024; i += 256) {
            int r  = i >> 4;
            int c4 = i & 15;
            float4 kv = *(const float4*)(kb + r * HS + c4 * 4);
            kst[(c4 * 4 + 0) * ATT_STRIDE + r] = kv.x;
            kst[(c4 * 4 + 1) * ATT_STRIDE + r] = kv.y;
            kst[(c4 * 4 + 2) * ATT_STRIDE + r] = kv.z;
            kst[(c4 * 4 + 3) * ATT_STRIDE + r] = kv.w;
            float4 vv = *(const float4*)(vb + r * HS + c4 * 4);
            *(float4*)&vs[r * ATT_STRIDE + c4 * 4] = vv;
        }
        __syncthreads();

        float sc[4][4];
        #pragma unroll
        for (int i = 0; i < 4; ++i)
            #pragma unroll
            for (int j = 0; j < 4; ++j) sc[i][j] = 0.0f;

        #pragma unroll 8
        for (int h = 0; h < 64; ++h) {
            float a0 = qs[(ty * 4 + 0) * ATT_STRIDE + h];
            float a1 = qs[(ty * 4 + 1) * ATT_STRIDE + h];
            float a2 = qs[(ty * 4 + 2) * ATT_STRIDE + h];
            float a3 = qs[(ty * 4 + 3) * ATT_STRIDE + h];
            float4 bb = *(const float4*)&kst[h * ATT_STRIDE + tx * 4];
            sc[0][0] += a0 * bb.x; sc[0][1] += a0 * bb.y; sc[0][2] += a0 * bb.z; sc[0][3] += a0 * bb.w;
            sc[1][0] += a1 * bb.x; sc[1][1] += a1 * bb.y; sc[1][2] += a1 * bb.z; sc[1][3] += a1 * bb.w;
            sc[2][0] += a2 * bb.x; sc[2][1] += a2 * bb.y; sc[2][2] += a2 * bb.z; sc[2][3] += a2 * bb.w;
            sc[3][0] += a3 * bb.x; sc[3][1] += a3 * bb.y; sc[3][2] += a3 * bb.z; sc[3][3] += a3 * bb.w;
        }

        const int qi0 = qt * 64 + ty * 4;
        const int kj0 = st * 64 + tx * 4;
        #pragma unroll
        for (int i = 0; i < 4; ++i)
            #pragma unroll
            for (int j = 0; j < 4; ++j) {
                float v = sc[i][j] * scale;
                if (kj0 + j > qi0 + i) v = -1e30f;
                sc[i][j] = v;
            }

        #pragma unroll
        for (int i = 0; i < 4; ++i) {
            float rmax = fmaxf(fmaxf(sc[i][0], sc[i][1]), fmaxf(sc[i][2], sc[i][3]));
            #pragma unroll
            for (int off = 8; off > 0; off >>= 1)
                rmax = fmaxf(rmax, __shfl_xor_sync(0xffffffffu, rmax, off, 16));
            float mnew  = fmaxf(m[i], rmax);
            float alpha = __expf(m[i] - mnew);
            float rsum  = 0.0f;
            #pragma unroll
            for (int j = 0; j < 4; ++j) {
                float p = __expf(sc[i][j] - mnew);
                ps[(ty * 4 + i) * ATT_STRIDE + tx * 4 + j] = p;
                rsum += p;
            }
            #pragma unroll
            for (int off = 8; off > 0; off >>= 1)
                rsum += __shfl_xor_sync(0xffffffffu, rsum, off, 16);
            l[i] = l[i] * alpha + rsum;
            m[i] = mnew;
            #pragma unroll
            for (int j = 0; j < 4; ++j) o[i][j] *= alpha;
        }
        __syncthreads();

        #pragma unroll 8
        for (int s2 = 0; s2 < 64; ++s2) {
            float a0 = ps[(ty * 4 + 0) * ATT_STRIDE + s2];
            float a1 = ps[(ty * 4 + 1) * ATT_STRIDE + s2];
            float a2 = ps[(ty * 4 + 2) * ATT_STRIDE + s2];
            float a3 = ps[(ty * 4 + 3) * ATT_STRIDE + s2];
            float4 bb = *(const float4*)&vs[s2 * ATT_STRIDE + tx * 4];
            o[0][0] += a0 * bb.x; o[0][1] += a0 * bb.y; o[0][2] += a0 * bb.z; o[0][3] += a0 * bb.w;
            o[1][0] += a1 * bb.x; o[1][1] += a1 * bb.y; o[1][2] += a1 * bb.z; o[1][3] += a1 * bb.w;
            o[2][0] += a2 * bb.x; o[2][1] += a2 * bb.y; o[2][2] += a2 * bb.z; o[2][3] += a2 * bb.w;
            o[3][0] += a3 * bb.x; o[3][1] += a3 * bb.y; o[3][2] += a3 * bb.z; o[3][3] += a3 * bb.w;
        }
        __syncthreads();
    }

    float* ob = out + ((size_t)b * BT + qt * 64) * HS;
    #pragma unroll
    for (int i = 0; i < 4; ++i) {
        float inv = 1.0f / l[i];
        float4 r4 = make_float4(o[i][0] * inv, o[i][1] * inv, o[i][2] * inv, o[i][3] * inv);
        *(float4*)(ob + (ty * 4 + i) * HS + tx * 4) = r4;
    }
}

// ---------------------------------------------------------------------------
// Launch
// ---------------------------------------------------------------------------
extern "C" void kernel_launch(void* const* d_in, const int* in_sizes, int n_in,
                              void* d_out, int out_size)
{
    (void)in_sizes; (void)n_in; (void)out_size;
    const float* x  = (const float*)d_in[0];
    const float* Wq = (const float*)d_in[1];
    const float* Wk = (const float*)d_in[2];
    const float* Wv = (const float*)d_in[3];
    float* out = (float*)d_out;

    cudaFuncSetAttribute(attn_kernel,
                         cudaFuncAttributeMaxDynamicSharedMemorySize,
                         ATT_SMEM_BYTES);

    // W -> combined bf16 hi/lo
    wconv_kernel<<<(3 * CE * HS + 255) / 256, 256>>>(Wq, Wk, Wv);

    // QKV projection on tensor cores: 262144 rows / 128 per CTA = 2048 CTAs
    qkv_proj_wmma<<<2048, 384>>>(x);

    // Attention: 4 query tiles x 1024 batches
    attn_kernel<<<dim3(4, NB), 256, ATT_SMEM_BYTES>>>(out);
}

// round 5
// speedup vs baseline: 1.9027x; 1.7008x over previous
#include <cuda_runtime.h>
#include <cuda_bf16.h>
#include <mma.h>
#include <cstdint>

using namespace nvcuda;

// Problem constants
#define NB    1024   // batch
#define BT    256    // block_size (seq len)
#define CE    384    // n_embed
#define HS    64     // head_size

// Scratch (device globals: no allocation allowed)
__device__ float g_q[(size_t)NB * BT * HS];
__device__ float g_k[(size_t)NB * BT * HS];
__device__ float g_v[(size_t)NB * BT * HS];
// Combined bf16 hi/lo weights: [CE][192] where cols = [Wq | Wk | Wv]
__device__ __nv_bfloat16 g_whc[CE * 192];
__device__ __nv_bfloat16 g_wlc[CE * 192];

// ---------------------------------------------------------------------------
// cp.async helpers (Ampere+ baseline PTX, fine on sm_103 non-a)
// ---------------------------------------------------------------------------
__device__ __forceinline__ uint32_t smem_u32(const void* p) {
    uint32_t a;
    asm("{ .reg .u64 t; cvta.to.shared.u64 t, %1; cvt.u32.u64 %0, t; }"
        : "=r"(a) : "l"(p));
    return a;
}
__device__ __forceinline__ void cp_async16(uint32_t dst, const void* src) {
    asm volatile("cp.async.ca.shared.global [%0], [%1], 16;"
                 :: "r"(dst), "l"(src) : "memory");
}
__device__ __forceinline__ void cp_commit() {
    asm volatile("cp.async.commit_group;" ::: "memory");
}
template <int N>
__device__ __forceinline__ void cp_wait() {
    asm volatile("cp.async.wait_group %0;" :: "n"(N) : "memory");
}

// ---------------------------------------------------------------------------
// Kernel 0: convert W (q,k,v) into combined bf16 hi/lo [CE][192].
// ---------------------------------------------------------------------------
__global__ void wconv_kernel(const float* __restrict__ Wq,
                             const float* __restrict__ Wk,
                             const float* __restrict__ Wv) {
    int i = blockIdx.x * blockDim.x + threadIdx.x;
    if (i >= 3 * CE * HS) return;
    int w = i / (CE * HS);
    int r = i % (CE * HS);
    int k = r / HS;
    int n = r % HS;
    const float* W = (w == 0) ? Wq : (w == 1) ? Wk : Wv;
    float v = W[k * HS + n];
    __nv_bfloat16 h = __float2bfloat16(v);
    __nv_bfloat16 l = __float2bfloat16(v - __bfloat162float(h));
    g_whc[k * 192 + w * 64 + n] = h;
    g_wlc[k * 192 + w * 64 + n] = l;
}

// ---------------------------------------------------------------------------
// Kernel 1: QKV projection on tensor cores (WMMA bf16, split hi/lo, 3 MMAs).
// CTA tile: 128 rows x 192 cols. 384 threads = 12 warps (4m x 3n).
// Double-buffered smem; cp.async for B; register-prefetch for A.
// A stride 40 (80B, conflict-free). B stride 200 (400B, conflict-free).
// ---------------------------------------------------------------------------
#define AST 40
#define BST 200
#define A_STAGE (2 * 128 * AST)    // elems per A stage (hi+lo)
#define A_LO    (128 * AST)        // lo offset within A stage
#define B_STAGE (2 * 32 * BST)     // elems per B stage (hi+lo)
#define B_LO    (32 * BST)
#define B_BASE  (2 * A_STAGE)      // b stages follow a stages
#define P_SMEM_BYTES ((2 * A_STAGE + 2 * B_STAGE) * 2)   // 92160 B

__global__ __launch_bounds__(384) void qkv_proj_wmma(const float* __restrict__ x)
{
    extern __shared__ __align__(16) __nv_bfloat16 sh[];

    const int tid = threadIdx.x;
    const int wrp = tid >> 5;
    const int wym = wrp / 3;         // 0..3 (m)
    const int wxn = wrp % 3;         // 0..2 (n -> q/k/v)
    const size_t rowBase = (size_t)blockIdx.x * 128;
    const uint32_t shb = smem_u32(sh);

    wmma::fragment<wmma::accumulator, 16, 16, 16, float> acc[2][4];
    #pragma unroll
    for (int i = 0; i < 2; ++i)
        #pragma unroll
        for (int j = 0; j < 4; ++j)
            wmma::fill_fragment(acc[i][j], 0.0f);

    // A-prefetch registers: up to 3 float4 per thread (1024 total / 384)
    float4 pre[3];
    const int ar[3]  = {tid >> 3, (tid + 384) >> 3, (tid + 768) >> 3};
    const int ac4[3] = {tid & 7, (tid + 384) & 7, (tid + 768) & 7};
    const bool av[3] = {true, true, tid < 256};

    // issue B cp.async for a chunk kc into stage st
    auto issueB = [&](int kc, int st) {
        #pragma unroll
        for (int p = 0; p < 4; ++p) {
            int i = tid + p * 384;            // 1536 chunks of 16B
            int isLo = i >> 9;                // 0..2 -> hi,lo ranges (i<1536)
            int rem  = i & 511;               // but 1536 = 2*768; fix below
            (void)rem;
            // i in [0,768): hi ; [768,1536): lo
            int lo = (i >= 768);
            int ii = lo ? i - 768 : i;        // 0..767 = 32 rows * 24 chunks
            int r  = ii / 24;
            int c  = ii % 24;
            (void)isLo;
            const __nv_bfloat16* src =
                (lo ? g_wlc : g_whc) + (size_t)(kc * 32 + r) * 192 + c * 8;
            uint32_t dst = shb + (uint32_t)(B_BASE + st * B_STAGE
                             + lo * B_LO + r * BST + c * 8) * 2;
            cp_async16(dst, src);
        }
        cp_commit();
    };
    // load A chunk kc into prefetch regs
    auto loadA = [&](int kc) {
        #pragma unroll
        for (int p = 0; p < 3; ++p)
            if (av[p])
                pre[p] = *(const float4*)(x + (rowBase + ar[p]) * CE
                                          + kc * 32 + ac4[p] * 4);
    };
    // convert prefetch regs into A stage st
    auto storeA = [&](int st) {
        #pragma unroll
        for (int p = 0; p < 3; ++p) {
            if (!av[p]) continue;
            float4 v = pre[p];
            float hx = __bfloat162float(__float2bfloat16(v.x));
            float hy = __bfloat162float(__float2bfloat16(v.y));
            float hz = __bfloat162float(__float2bfloat16(v.z));
            float hw = __bfloat162float(__float2bfloat16(v.w));
            __nv_bfloat162 h01 = __floats2bfloat162_rn(v.x, v.y);
            __nv_bfloat162 h23 = __floats2bfloat162_rn(v.z, v.w);
            __nv_bfloat162 l01 = __floats2bfloat162_rn(v.x - hx, v.y - hy);
            __nv_bfloat162 l23 = __floats2bfloat162_rn(v.z - hz, v.w - hw);
            __nv_bfloat16* base = sh + st * A_STAGE + ar[p] * AST + ac4[p] * 4;
            ((__nv_bfloat162*)base)[0] = h01;
            ((__nv_bfloat162*)base)[1] = h23;
            ((__nv_bfloat162*)(base + A_LO))[0] = l01;
            ((__nv_bfloat162*)(base + A_LO))[1] = l23;
        }
    };

    // prologue: stage 0 for chunk 0
    loadA(0);
    issueB(0, 0);
    storeA(0);

    for (int kc = 0; kc < 12; ++kc) {
        const int buf = kc & 1;
        if (kc < 11) {
            loadA(kc + 1);              // global loads in flight during waits
            issueB(kc + 1, buf ^ 1);    // cp.async into other stage
            cp_wait<1>();               // chunk kc's B group done
        } else {
            cp_wait<0>();
        }
        __syncthreads();                // A+B of stage buf visible to all

        const __nv_bfloat16* aS = sh + buf * A_STAGE;
        const __nv_bfloat16* bS = sh + B_BASE + buf * B_STAGE;

        #pragma unroll
        for (int ks = 0; ks < 2; ++ks) {
            wmma::fragment<wmma::matrix_a, 16, 16, 16, __nv_bfloat16, wmma::row_major> ah[2], al[2];
            wmma::fragment<wmma::matrix_b, 16, 16, 16, __nv_bfloat16, wmma::row_major> bh[4], bl[4];
            #pragma unroll
            for (int i = 0; i < 2; ++i) {
                const __nv_bfloat16* pa = aS + (wym * 32 + i * 16) * AST + ks * 16;
                wmma::load_matrix_sync(ah[i], pa, AST);
                wmma::load_matrix_sync(al[i], pa + A_LO, AST);
            }
            #pragma unroll
            for (int j = 0; j < 4; ++j) {
                const __nv_bfloat16* pb = bS + (ks * 16) * BST + wxn * 64 + j * 16;
                wmma::load_matrix_sync(bh[j], pb, BST);
                wmma::load_matrix_sync(bl[j], pb + B_LO, BST);
            }
            #pragma unroll
            for (int i = 0; i < 2; ++i)
                #pragma unroll
                for (int j = 0; j < 4; ++j) {
                    wmma::mma_sync(acc[i][j], ah[i], bh[j], acc[i][j]);
                    wmma::mma_sync(acc[i][j], ah[i], bl[j], acc[i][j]);
                    wmma::mma_sync(acc[i][j], al[i], bh[j], acc[i][j]);
                }
        }
        __syncthreads();                // stage buf free for reuse
        if (kc < 11) storeA(buf ^ 1);   // convert next chunk into other stage
    }

    // --- epilogue: each warp's 64-col range is exactly one of q/k/v ---
    float* dst = (wxn == 0) ? g_q : (wxn == 1) ? g_k : g_v;
    #pragma unroll
    for (int i = 0; i < 2; ++i) {
        size_t row = rowBase + wym * 32 + i * 16;
        #pragma unroll
        for (int j = 0; j < 4; ++j)
            wmma::store_matrix_sync(dst + row * HS + j * 16, acc[i][j], HS,
                                    wmma::mem_row_major);
    }
}

// ---------------------------------------------------------------------------
// Kernel 2: fused causal flash attention over q,k,v (fp32). (unchanged)
// ---------------------------------------------------------------------------
#define ATT_STRIDE 68
#define ATT_SMEM_BYTES (4 * 64 * ATT_STRIDE * 4)   // 69632 B

__global__ __launch_bounds__(256) void attn_kernel(float* __restrict__ out)
{
    extern __shared__ float sm[];
    float* qs  = sm;                       // [row][h]   stride 68
    float* kst = sm + 64 * ATT_STRIDE;     // [h][key]   stride 68
    float* vs  = sm + 2 * 64 * ATT_STRIDE; // [key][h]   stride 68
    float* ps  = sm + 3 * 64 * ATT_STRIDE; // [row][key] stride 68

    const int b   = blockIdx.y;
    const int qt  = blockIdx.x;
    const int tid = threadIdx.x;
    const int tx  = tid & 15;
    const int ty  = tid >> 4;
    const float scale = 0.05103103630798288f;   // 384^-0.5

    const float* qb = g_q + ((size_t)b * BT + qt * 64) * HS;
    for (int i = tid; i < 1024; i += 256) {
        int r  = i >> 4;
        int c4 = i & 15;
        float4 v = *(const float4*)(qb + r * HS + c4 * 4);
        *(float4*)&qs[r * ATT_STRIDE + c4 * 4] = v;
    }

    float m[4], l[4], o[4][4];
    #pragma unroll
    for (int i = 0; i < 4; ++i) {
        m[i] = -1e30f;
        l[i] = 0.0f;
        #pragma unroll
        for (int j = 0; j < 4; ++j) o[i][j] = 0.0f;
    }

    for (int st = 0; st <= qt; ++st) {
        const float* kb = g_k + ((size_t)b * BT + st * 64) * HS;
        const float* vb = g_v + ((size_t)b * BT + st * 64) * HS;
        for (int i = tid; i < 1024; i += 256) {
            int r  = i >> 4;
            int c4 = i & 15;
            float4 kv = *(const float4*)(kb + r * HS + c4 * 4);
            kst[(c4 * 4 + 0) * ATT_STRIDE + r] = kv.x;
            kst[(c4 * 4 + 1) * ATT_STRIDE + r] = kv.y;
            kst[(c4 * 4 + 2) * ATT_STRIDE + r] = kv.z;
            kst[(c4 * 4 + 3) * ATT_STRIDE + r] = kv.w;
            float4 vv = *(const float4*)(vb + r * HS + c4 * 4);
            *(float4*)&vs[r * ATT_STRIDE + c4 * 4] = vv;
        }
        __syncthreads();

        float sc[4][4];
        #pragma unroll
        for (int i = 0; i < 4; ++i)
            #pragma unroll
            for (int j = 0; j < 4; ++j) sc[i][j] = 0.0f;

        #pragma unroll 8
        for (int h = 0; h < 64; ++h) {
            float a0 = qs[(ty * 4 + 0) * ATT_STRIDE + h];
            float a1 = qs[(ty * 4 + 1) * ATT_STRIDE + h];
            float a2 = qs[(ty * 4 + 2) * ATT_STRIDE + h];
            float a3 = qs[(ty * 4 + 3) * ATT_STRIDE + h];
            float4 bb = *(const float4*)&kst[h * ATT_STRIDE + tx * 4];
            sc[0][0] += a0 * bb.x; sc[0][1] += a0 * bb.y; sc[0][2] += a0 * bb.z; sc[0][3] += a0 * bb.w;
            sc[1][0] += a1 * bb.x; sc[1][1] += a1 * bb.y; sc[1][2] += a1 * bb.z; sc[1][3] += a1 * bb.w;
            sc[2][0] += a2 * bb.x; sc[2][1] += a2 * bb.y; sc[2][2] += a2 * bb.z; sc[2][3] += a2 * bb.w;
            sc[3][0] += a3 * bb.x; sc[3][1] += a3 * bb.y; sc[3][2] += a3 * bb.z; sc[3][3] += a3 * bb.w;
        }

        const int qi0 = qt * 64 + ty * 4;
        const int kj0 = st * 64 + tx * 4;
        #pragma unroll
        for (int i = 0; i < 4; ++i)
            #pragma unroll
            for (int j = 0; j < 4; ++j) {
                float v = sc[i][j] * scale;
                if (kj0 + j > qi0 + i) v = -1e30f;
                sc[i][j] = v;
            }

        #pragma unroll
        for (int i = 0; i < 4; ++i) {
            float rmax = fmaxf(fmaxf(sc[i][0], sc[i][1]), fmaxf(sc[i][2], sc[i][3]));
            #pragma unroll
            for (int off = 8; off > 0; off >>= 1)
                rmax = fmaxf(rmax, __shfl_xor_sync(0xffffffffu, rmax, off, 16));
            float mnew  = fmaxf(m[i], rmax);
            float alpha = __expf(m[i] - mnew);
            float rsum  = 0.0f;
            #pragma unroll
            for (int j = 0; j < 4; ++j) {
                float p = __expf(sc[i][j] - mnew);
                ps[(ty * 4 + i) * ATT_STRIDE + tx * 4 + j] = p;
                rsum += p;
            }
            #pragma unroll
            for (int off = 8; off > 0; off >>= 1)
                rsum += __shfl_xor_sync(0xffffffffu, rsum, off, 16);
            l[i] = l[i] * alpha + rsum;
            m[i] = mnew;
            #pragma unroll
            for (int j = 0; j < 4; ++j) o[i][j] *= alpha;
        }
        __syncthreads();

        #pragma unroll 8
        for (int s2 = 0; s2 < 64; ++s2) {
            float a0 = ps[(ty * 4 + 0) * ATT_STRIDE + s2];
            float a1 = ps[(ty * 4 + 1) * ATT_STRIDE + s2];
            float a2 = ps[(ty * 4 + 2) * ATT_STRIDE + s2];
            float a3 = ps[(ty * 4 + 3) * ATT_STRIDE + s2];
            float4 bb = *(const float4*)&vs[s2 * ATT_STRIDE + tx * 4];
            o[0][0] += a0 * bb.x; o[0][1] += a0 * bb.y; o[0][2] += a0 * bb.z; o[0][3] += a0 * bb.w;
            o[1][0] += a1 * bb.x; o[1][1] += a1 * bb.y; o[1][2] += a1 * bb.z; o[1][3] += a1 * bb.w;
            o[2][0] += a2 * bb.x; o[2][1] += a2 * bb.y; o[2][2] += a2 * bb.z; o[2][3] += a2 * bb.w;
            o[3][0] += a3 * bb.x; o[3][1] += a3 * bb.y; o[3][2] += a3 * bb.z; o[3][3] += a3 * bb.w;
        }
        __syncthreads();
    }

    float* ob = out + ((size_t)b * BT + qt * 64) * HS;
    #pragma unroll
    for (int i = 0; i < 4; ++i) {
        float inv = 1.0f / l[i];
        float4 r4 = make_float4(o[i][0] * inv, o[i][1] * inv, o[i][2] * inv, o[i][3] * inv);
        *(float4*)(ob + (ty * 4 + i) * HS + tx * 4) = r4;
    }
}

// ---------------------------------------------------------------------------
// Launch
// ---------------------------------------------------------------------------
extern "C" void kernel_launch(void* const* d_in, const int* in_sizes, int n_in,
                              void* d_out, int out_size)
{
    (void)in_sizes; (void)n_in; (void)out_size;
    const float* x  = (const float*)d_in[0];
    const float* Wq = (const float*)d_in[1];
    const float* Wk = (const float*)d_in[2];
    const float* Wv = (const float*)d_in[3];
    float* out = (float*)d_out;

    cudaFuncSetAttribute(qkv_proj_wmma,
                         cudaFuncAttributeMaxDynamicSharedMemorySize,
                         P_SMEM_BYTES);
    cudaFuncSetAttribute(attn_kernel,
                         cudaFuncAttributeMaxDynamicSharedMemorySize,
                         ATT_SMEM_BYTES);

    // W -> combined bf16 hi/lo
    wconv_kernel<<<(3 * CE * HS + 255) / 256, 256>>>(Wq, Wk, Wv);

    // QKV projection on tensor cores: 262144 rows / 128 per CTA = 2048 CTAs
    qkv_proj_wmma<<<2048, 384, P_SMEM_BYTES>>>(x);

    // Attention: 4 query tiles x 1024 batches
    attn_kernel<<<dim3(4, NB), 256, ATT_SMEM_BYTES>>>(out);
}

// round 6
// speedup vs baseline: 2.7687x; 1.4551x over previous
#include <cuda_runtime.h>
#include <cuda_fp16.h>
#include <mma.h>
#include <cstdint>

using namespace nvcuda;

// Problem constants
#define NB    1024   // batch
#define BT    256    // block_size (seq len)
#define CE    384    // n_embed
#define HS    64     // head_size

// Scratch (device globals: no allocation allowed)
__device__ float g_q[(size_t)NB * BT * HS];
__device__ float g_k[(size_t)NB * BT * HS];
__device__ float g_v[(size_t)NB * BT * HS];
// Combined fp16 weights: [CE][192] where cols = [Wq | Wk | Wv]
__device__ __half g_wh[CE * 192];

// ---------------------------------------------------------------------------
// helpers
// ---------------------------------------------------------------------------
__device__ __forceinline__ uint32_t smem_u32(const void* p) {
    uint32_t a;
    asm("{ .reg .u64 t; cvta.to.shared.u64 t, %1; cvt.u32.u64 %0, t; }"
        : "=r"(a) : "l"(p));
    return a;
}
__device__ __forceinline__ void cp_async16(uint32_t dst, const void* src) {
    asm volatile("cp.async.ca.shared.global [%0], [%1], 16;"
                 :: "r"(dst), "l"(src) : "memory");
}
__device__ __forceinline__ void cp_commit() {
    asm volatile("cp.async.commit_group;" ::: "memory");
}
template <int N>
__device__ __forceinline__ void cp_wait() {
    asm volatile("cp.async.wait_group %0;" :: "n"(N) : "memory");
}

// Fast exp on the FMA pipe (no MUFU). |rel err| ~2.4e-6 on valid range.
// Valid for x <= ~0 (clamped at -87 -> returns ~1.6e-38 ~= 0).
__device__ __forceinline__ float fast_exp(float x) {
    x = fmaxf(x, -87.0f);
    float r = x * 1.4426950408889634f;          // x * log2(e), in [-125.5, ~]
    float kf = r + 12582912.0f;                 // 1.5 * 2^23: round-to-nearest
    float i  = kf - 12582912.0f;                // rintf(r)
    float f  = r - i;                           // [-0.5, 0.5]
    // 2^f, degree-5 Taylor (max rel err ~2.4e-6 on [-0.5,0.5])
    float p = 0.0013333558f;
    p = fmaf(p, f, 0.0096181291f);
    p = fmaf(p, f, 0.0555041087f);
    p = fmaf(p, f, 0.2402265069f);
    p = fmaf(p, f, 0.6931471806f);
    p = fmaf(p, f, 1.0f);
    int ik = __float_as_int(kf) - 0x4B400000;   // integer part of r
    float scale = __int_as_float((ik + 127) << 23);
    return p * scale;
}

// ---------------------------------------------------------------------------
// Kernel 0: convert W (q,k,v) into combined fp16 [CE][192].
// ---------------------------------------------------------------------------
__global__ void wconv_kernel(const float* __restrict__ Wq,
                             const float* __restrict__ Wk,
                             const float* __restrict__ Wv) {
    int i = blockIdx.x * blockDim.x + threadIdx.x;
    if (i >= 3 * CE * HS) return;
    int w = i / (CE * HS);
    int r = i % (CE * HS);
    int k = r / HS;
    int n = r % HS;
    const float* W = (w == 0) ? Wq : (w == 1) ? Wk : Wv;
    g_wh[k * 192 + w * 64 + n] = __float2half_rn(W[k * HS + n]);
}

// ---------------------------------------------------------------------------
// Kernel 1: QKV projection on tensor cores (WMMA fp16 single-term).
// CTA tile: 128 rows x 192 cols. 384 threads = 12 warps (4m x 3n).
// Double-buffered smem; cp.async for B; register-prefetch for A.
// A stride 40 (80B, conflict-free ldmatrix). B stride 200 (400B, CF).
// ---------------------------------------------------------------------------
#define AST 40
#define BST 200
#define A_STAGE (128 * AST)        // elems per A stage
#define B_STAGE (32 * BST)         // elems per B stage
#define B_BASE  (2 * A_STAGE)      // b stages follow a stages
#define P_SMEM_BYTES ((2 * A_STAGE + 2 * B_STAGE) * 2)   // 46080 B

__global__ __launch_bounds__(384) void qkv_proj_wmma(const float* __restrict__ x)
{
    extern __shared__ __align__(16) __half sh[];

    const int tid = threadIdx.x;
    const int wrp = tid >> 5;
    const int wym = wrp / 3;         // 0..3 (m)
    const int wxn = wrp % 3;         // 0..2 (n -> q/k/v)
    const size_t rowBase = (size_t)blockIdx.x * 128;
    const uint32_t shb = smem_u32(sh);

    wmma::fragment<wmma::accumulator, 16, 16, 16, float> acc[2][4];
    #pragma unroll
    for (int i = 0; i < 2; ++i)
        #pragma unroll
        for (int j = 0; j < 4; ++j)
            wmma::fill_fragment(acc[i][j], 0.0f);

    // A-prefetch registers: up to 3 float4 per thread (1024 total / 384)
    float4 pre[3];
    const int ar[3]  = {tid >> 3, (tid + 384) >> 3, (tid + 768) >> 3};
    const int ac4[3] = {tid & 7, (tid + 384) & 7, (tid + 768) & 7};
    const bool av[3] = {true, true, tid < 256};

    // issue B cp.async for chunk kc into stage st (768 x 16B)
    auto issueB = [&](int kc, int st) {
        #pragma unroll
        for (int p = 0; p < 2; ++p) {
            int i = tid + p * 384;            // 0..767 = 32 rows * 24 chunks
            int r = i / 24;
            int c = i % 24;
            const __half* src = g_wh + (size_t)(kc * 32 + r) * 192 + c * 8;
            uint32_t dst = shb + (uint32_t)(B_BASE + st * B_STAGE
                             + r * BST + c * 8) * 2;
            cp_async16(dst, src);
        }
        cp_commit();
    };
    auto loadA = [&](int kc) {
        #pragma unroll
        for (int p = 0; p < 3; ++p)
            if (av[p])
                pre[p] = *(const float4*)(x + (rowBase + ar[p]) * CE
                                          + kc * 32 + ac4[p] * 4);
    };
    auto storeA = [&](int st) {
        #pragma unroll
        for (int p = 0; p < 3; ++p) {
            if (!av[p]) continue;
            float4 v = pre[p];
            __half2 h01 = __floats2half2_rn(v.x, v.y);
            __half2 h23 = __floats2half2_rn(v.z, v.w);
            __half* base = sh + st * A_STAGE + ar[p] * AST + ac4[p] * 4;
            ((__half2*)base)[0] = h01;
            ((__half2*)base)[1] = h23;
        }
    };

    // prologue: stage 0 for chunk 0
    loadA(0);
    issueB(0, 0);
    storeA(0);

    for (int kc = 0; kc < 12; ++kc) {
        const int buf = kc & 1;
        if (kc < 11) {
            loadA(kc + 1);
            issueB(kc + 1, buf ^ 1);
            cp_wait<1>();
        } else {
            cp_wait<0>();
        }
        __syncthreads();

        const __half* aS = sh + buf * A_STAGE;
        const __half* bS = sh + B_BASE + buf * B_STAGE;

        #pragma unroll
        for (int ks = 0; ks < 2; ++ks) {
            wmma::fragment<wmma::matrix_a, 16, 16, 16, __half, wmma::row_major> a[2];
            wmma::fragment<wmma::matrix_b, 16, 16, 16, __half, wmma::row_major> b[4];
            #pragma unroll
            for (int i = 0; i < 2; ++i)
                wmma::load_matrix_sync(a[i], aS + (wym * 32 + i * 16) * AST + ks * 16, AST);
            #pragma unroll
            for (int j = 0; j < 4; ++j)
                wmma::load_matrix_sync(b[j], bS + (ks * 16) * BST + wxn * 64 + j * 16, BST);
            #pragma unroll
            for (int i = 0; i < 2; ++i)
                #pragma unroll
                for (int j = 0; j < 4; ++j)
                    wmma::mma_sync(acc[i][j], a[i], b[j], acc[i][j]);
        }
        __syncthreads();
        if (kc < 11) storeA(buf ^ 1);
    }

    // --- epilogue: each warp's 64-col range is exactly one of q/k/v ---
    float* dst = (wxn == 0) ? g_q : (wxn == 1) ? g_k : g_v;
    #pragma unroll
    for (int i = 0; i < 2; ++i) {
        size_t row = rowBase + wym * 32 + i * 16;
        #pragma unroll
        for (int j = 0; j < 4; ++j)
            wmma::store_matrix_sync(dst + row * HS + j * 16, acc[i][j], HS,
                                    wmma::mem_row_major);
    }
}

// ---------------------------------------------------------------------------
// Kernel 2: fused causal flash attention over q,k,v (fp32).
// Same as R5 except __expf -> fast_exp (FMA pipe, no MUFU).
// ---------------------------------------------------------------------------
#define ATT_STRIDE 68
#define ATT_SMEM_BYTES (4 * 64 * ATT_STRIDE * 4)   // 69632 B

__global__ __launch_bounds__(256) void attn_kernel(float* __restrict__ out)
{
    extern __shared__ float sm[];
    float* qs  = sm;                       // [row][h]   stride 68
    float* kst = sm + 64 * ATT_STRIDE;     // [h][key]   stride 68
    float* vs  = sm + 2 * 64 * ATT_STRIDE; // [key][h]   stride 68
    float* ps  = sm + 3 * 64 * ATT_STRIDE; // [row][key] stride 68

    const int b   = blockIdx.y;
    const int qt  = blockIdx.x;
    const int tid = threadIdx.x;
    const int tx  = tid & 15;
    const int ty  = tid >> 4;
    const float scale = 0.05103103630798288f;   // 384^-0.5

    const float* qb = g_q + ((size_t)b * BT + qt * 64) * HS;
    for (int i = tid; i < 1024; i += 256) {
        int r  = i >> 4;
        int c4 = i & 15;
        float4 v = *(const float4*)(qb + r * HS + c4 * 4);
        *(float4*)&qs[r * ATT_STRIDE + c4 * 4] = v;
    }

    float m[4], l[4], o[4][4];
    #pragma unroll
    for (int i = 0; i < 4; ++i) {
        m[i] = -1e30f;
        l[i] = 0.0f;
        #pragma unroll
        for (int j = 0; j < 4; ++j) o[i][j] = 0.0f;
    }

    for (int st = 0; st <= qt; ++st) {
        const float* kb = g_k + ((size_t)b * BT + st * 64) * HS;
        const float* vb = g_v + ((size_t)b * BT + st * 64) * HS;
        for (int i = tid; i < 1024; i += 256) {
            int r  = i >> 4;
            int c4 = i & 15;
            float4 kv = *(const float4*)(kb + r * HS + c4 * 4);
            kst[(c4 * 4 + 0) * ATT_STRIDE + r] = kv.x;
            kst[(c4 * 4 + 1) * ATT_STRIDE + r] = kv.y;
            kst[(c4 * 4 + 2) * ATT_STRIDE + r] = kv.z;
            kst[(c4 * 4 + 3) * ATT_STRIDE + r] = kv.w;
            float4 vv = *(const float4*)(vb + r * HS + c4 * 4);
            *(float4*)&vs[r * ATT_STRIDE + c4 * 4] = vv;
        }
        __syncthreads();

        float sc[4][4];
        #pragma unroll
        for (int i = 0; i < 4; ++i)
            #pragma unroll
            for (int j = 0; j < 4; ++j) sc[i][j] = 0.0f;

        #pragma unroll 8
        for (int h = 0; h < 64; ++h) {
            float a0 = qs[(ty * 4 + 0) * ATT_STRIDE + h];
            float a1 = qs[(ty * 4 + 1) * ATT_STRIDE + h];
            float a2 = qs[(ty * 4 + 2) * ATT_STRIDE + h];
            float a3 = qs[(ty * 4 + 3) * ATT_STRIDE + h];
            float4 bb = *(const float4*)&kst[h * ATT_STRIDE + tx * 4];
            sc[0][0] += a0 * bb.x; sc[0][1] += a0 * bb.y; sc[0][2] += a0 * bb.z; sc[0][3] += a0 * bb.w;
            sc[1][0] += a1 * bb.x; sc[1][1] += a1 * bb.y; sc[1][2] += a1 * bb.z; sc[1][3] += a1 * bb.w;
            sc[2][0] += a2 * bb.x; sc[2][1] += a2 * bb.y; sc[2][2] += a2 * bb.z; sc[2][3] += a2 * bb.w;
            sc[3][0] += a3 * bb.x; sc[3][1] += a3 * bb.y; sc[3][2] += a3 * bb.z; sc[3][3] += a3 * bb.w;
        }

        const int qi0 = qt * 64 + ty * 4;
        const int kj0 = st * 64 + tx * 4;
        #pragma unroll
        for (int i = 0; i < 4; ++i)
            #pragma unroll
            for (int j = 0; j < 4; ++j) {
                float v = sc[i][j] * scale;
                if (kj0 + j > qi0 + i) v = -1e30f;
                sc[i][j] = v;
            }

        #pragma unroll
        for (int i = 0; i < 4; ++i) {
            float rmax = fmaxf(fmaxf(sc[i][0], sc[i][1]), fmaxf(sc[i][2], sc[i][3]));
            #pragma unroll
            for (int off = 8; off > 0; off >>= 1)
                rmax = fmaxf(rmax, __shfl_xor_sync(0xffffffffu, rmax, off, 16));
            float mnew  = fmaxf(m[i], rmax);
            float alpha = fast_exp(m[i] - mnew);
            float rsum  = 0.0f;
            #pragma unroll
            for (int j = 0; j < 4; ++j) {
                float p = fast_exp(sc[i][j] - mnew);
                ps[(ty * 4 + i) * ATT_STRIDE + tx * 4 + j] = p;
                rsum += p;
            }
            #pragma unroll
            for (int off = 8; off > 0; off >>= 1)
                rsum += __shfl_xor_sync(0xffffffffu, rsum, off, 16);
            l[i] = l[i] * alpha + rsum;
            m[i] = mnew;
            #pragma unroll
            for (int j = 0; j < 4; ++j) o[i][j] *= alpha;
        }
        __syncthreads();

        #pragma unroll 8
        for (int s2 = 0; s2 < 64; ++s2) {
            float a0 = ps[(ty * 4 + 0) * ATT_STRIDE + s2];
            float a1 = ps[(ty * 4 + 1) * ATT_STRIDE + s2];
            float a2 = ps[(ty * 4 + 2) * ATT_STRIDE + s2];
            float a3 = ps[(ty * 4 + 3) * ATT_STRIDE + s2];
            float4 bb = *(const float4*)&vs[s2 * ATT_STRIDE + tx * 4];
            o[0][0] += a0 * bb.x; o[0][1] += a0 * bb.y; o[0][2] += a0 * bb.z; o[0][3] += a0 * bb.w;
            o[1][0] += a1 * bb.x; o[1][1] += a1 * bb.y; o[1][2] += a1 * bb.z; o[1][3] += a1 * bb.w;
            o[2][0] += a2 * bb.x; o[2][1] += a2 * bb.y; o[2][2] += a2 * bb.z; o[2][3] += a2 * bb.w;
            o[3][0] += a3 * bb.x; o[3][1] += a3 * bb.y; o[3][2] += a3 * bb.z; o[3][3] += a3 * bb.w;
        }
        __syncthreads();
    }

    float* ob = out + ((size_t)b * BT + qt * 64) * HS;
    #pragma unroll
    for (int i = 0; i < 4; ++i) {
        float inv = 1.0f / l[i];
        float4 r4 = make_float4(o[i][0] * inv, o[i][1] * inv, o[i][2] * inv, o[i][3] * inv);
        *(float4*)(ob + (ty * 4 + i) * HS + tx * 4) = r4;
    }
}

// ---------------------------------------------------------------------------
// Launch
// ---------------------------------------------------------------------------
extern "C" void kernel_launch(void* const* d_in, const int* in_sizes, int n_in,
                              void* d_out, int out_size)
{
    (void)in_sizes; (void)n_in; (void)out_size;
    const float* x  = (const float*)d_in[0];
    const float* Wq = (const float*)d_in[1];
    const float* Wk = (const float*)d_in[2];
    const float* Wv = (const float*)d_in[3];
    float* out = (float*)d_out;

    cudaFuncSetAttribute(qkv_proj_wmma,
                         cudaFuncAttributeMaxDynamicSharedMemorySize,
                         P_SMEM_BYTES);
    cudaFuncSetAttribute(attn_kernel,
                         cudaFuncAttributeMaxDynamicSharedMemorySize,
                         ATT_SMEM_BYTES);

    // W -> combined fp16
    wconv_kernel<<<(3 * CE * HS + 255) / 256, 256>>>(Wq, Wk, Wv);

    // QKV projection on tensor cores: 262144 rows / 128 per CTA = 2048 CTAs
    qkv_proj_wmma<<<2048, 384, P_SMEM_BYTES>>>(x);

    // Attention: 4 query tiles x 1024 batches
    attn_kernel<<<dim3(4, NB), 256, ATT_SMEM_BYTES>>>(out);
}

// round 7
// speedup vs baseline: 4.1653x; 1.5044x over previous
#include <cuda_runtime.h>
#include <cuda_fp16.h>
#include <mma.h>
#include <cstdint>

using namespace nvcuda;

// Problem constants
#define NB    1024   // batch
#define BT    256    // block_size (seq len)
#define CE    384    // n_embed
#define HS    64     // head_size

// Scratch (device globals: no allocation allowed)
__device__ float g_q[(size_t)NB * BT * HS];
__device__ float g_k[(size_t)NB * BT * HS];
__device__ float g_v[(size_t)NB * BT * HS];
// Combined fp16 weights: [CE][192] where cols = [Wq | Wk | Wv]
__device__ __half g_wh[CE * 192];

// ---------------------------------------------------------------------------
// helpers
// ---------------------------------------------------------------------------
__device__ __forceinline__ uint32_t smem_u32(const void* p) {
    uint32_t a;
    asm("{ .reg .u64 t; cvta.to.shared.u64 t, %1; cvt.u32.u64 %0, t; }"
        : "=r"(a) : "l"(p));
    return a;
}
__device__ __forceinline__ void cp_async16(uint32_t dst, const void* src) {
    asm volatile("cp.async.ca.shared.global [%0], [%1], 16;"
                 :: "r"(dst), "l"(src) : "memory");
}
__device__ __forceinline__ void cp_commit() {
    asm volatile("cp.async.commit_group;" ::: "memory");
}
template <int N>
__device__ __forceinline__ void cp_wait() {
    asm volatile("cp.async.wait_group %0;" :: "n"(N) : "memory");
}

// Fast exp on the FMA pipe (no MUFU). |rel err| ~2.4e-6.
__device__ __forceinline__ float fast_exp(float x) {
    x = fmaxf(x, -87.0f);
    float r = x * 1.4426950408889634f;
    float kf = r + 12582912.0f;                 // 1.5*2^23 round-to-nearest
    float i  = kf - 12582912.0f;
    float f  = r - i;
    float p = 0.0013333558f;
    p = fmaf(p, f, 0.0096181291f);
    p = fmaf(p, f, 0.0555041087f);
    p = fmaf(p, f, 0.2402265069f);
    p = fmaf(p, f, 0.6931471806f);
    p = fmaf(p, f, 1.0f);
    int ik = __float_as_int(kf) - 0x4B400000;
    float scale = __int_as_float((ik + 127) << 23);
    return p * scale;
}

// mma.sync m16n8k16 fp16 -> fp32 (baseline PTX, valid on sm_103)
__device__ __forceinline__ void mma16816(float* c, const uint32_t* a, const uint32_t* b) {
    asm volatile(
        "mma.sync.aligned.m16n8k16.row.col.f32.f16.f16.f32 "
        "{%0,%1,%2,%3}, {%4,%5,%6,%7}, {%8,%9}, {%0,%1,%2,%3};"
        : "+f"(c[0]), "+f"(c[1]), "+f"(c[2]), "+f"(c[3])
        : "r"(a[0]), "r"(a[1]), "r"(a[2]), "r"(a[3]), "r"(b[0]), "r"(b[1]));
}
__device__ __forceinline__ void ldsm_x4(uint32_t* r, uint32_t addr) {
    asm volatile("ldmatrix.sync.aligned.m8n8.x4.shared.b16 {%0,%1,%2,%3}, [%4];"
                 : "=r"(r[0]), "=r"(r[1]), "=r"(r[2]), "=r"(r[3]) : "r"(addr));
}
__device__ __forceinline__ void ldsm_x4_t(uint32_t* r, uint32_t addr) {
    asm volatile("ldmatrix.sync.aligned.m8n8.x4.trans.shared.b16 {%0,%1,%2,%3}, [%4];"
                 : "=r"(r[0]), "=r"(r[1]), "=r"(r[2]), "=r"(r[3]) : "r"(addr));
}
__device__ __forceinline__ uint32_t pack_h2(__half a, __half b) {
    __half2 t = __halves2half2(a, b);
    return *reinterpret_cast<uint32_t*>(&t);
}

// ---------------------------------------------------------------------------
// Kernel 0: convert W (q,k,v) into combined fp16 [CE][192].
// ---------------------------------------------------------------------------
__global__ void wconv_kernel(const float* __restrict__ Wq,
                             const float* __restrict__ Wk,
                             const float* __restrict__ Wv) {
    int i = blockIdx.x * blockDim.x + threadIdx.x;
    if (i >= 3 * CE * HS) return;
    int w = i / (CE * HS);
    int r = i % (CE * HS);
    int k = r / HS;
    int n = r % HS;
    const float* W = (w == 0) ? Wq : (w == 1) ? Wk : Wv;
    g_wh[k * 192 + w * 64 + n] = __float2half_rn(W[k * HS + n]);
}

// ---------------------------------------------------------------------------
// Kernel 1: QKV projection (WMMA fp16, unchanged from R6 — near its roofline)
// ---------------------------------------------------------------------------
#define AST 40
#define BST 200
#define A_STAGE (128 * AST)
#define B_STAGE (32 * BST)
#define B_BASE  (2 * A_STAGE)
#define P_SMEM_BYTES ((2 * A_STAGE + 2 * B_STAGE) * 2)   // 46080 B

__global__ __launch_bounds__(384) void qkv_proj_wmma(const float* __restrict__ x)
{
    extern __shared__ __align__(16) __half sh[];

    const int tid = threadIdx.x;
    const int wrp = tid >> 5;
    const int wym = wrp / 3;
    const int wxn = wrp % 3;
    const size_t rowBase = (size_t)blockIdx.x * 128;
    const uint32_t shb = smem_u32(sh);

    wmma::fragment<wmma::accumulator, 16, 16, 16, float> acc[2][4];
    #pragma unroll
    for (int i = 0; i < 2; ++i)
        #pragma unroll
        for (int j = 0; j < 4; ++j)
            wmma::fill_fragment(acc[i][j], 0.0f);

    float4 pre[3];
    const int ar[3]  = {tid >> 3, (tid + 384) >> 3, (tid + 768) >> 3};
    const int ac4[3] = {tid & 7, (tid + 384) & 7, (tid + 768) & 7};
    const bool av[3] = {true, true, tid < 256};

    auto issueB = [&](int kc, int st) {
        #pragma unroll
        for (int p = 0; p < 2; ++p) {
            int i = tid + p * 384;
            int r = i / 24;
            int c = i % 24;
            const __half* src = g_wh + (size_t)(kc * 32 + r) * 192 + c * 8;
            uint32_t dst = shb + (uint32_t)(B_BASE + st * B_STAGE
                             + r * BST + c * 8) * 2;
            cp_async16(dst, src);
        }
        cp_commit();
    };
    auto loadA = [&](int kc) {
        #pragma unroll
        for (int p = 0; p < 3; ++p)
            if (av[p])
                pre[p] = *(const float4*)(x + (rowBase + ar[p]) * CE
                                          + kc * 32 + ac4[p] * 4);
    };
    auto storeA = [&](int st) {
        #pragma unroll
        for (int p = 0; p < 3; ++p) {
            if (!av[p]) continue;
            float4 v = pre[p];
            __half2 h01 = __floats2half2_rn(v.x, v.y);
            __half2 h23 = __floats2half2_rn(v.z, v.w);
            __half* base = sh + st * A_STAGE + ar[p] * AST + ac4[p] * 4;
            ((__half2*)base)[0] = h01;
            ((__half2*)base)[1] = h23;
        }
    };

    loadA(0);
    issueB(0, 0);
    storeA(0);

    for (int kc = 0; kc < 12; ++kc) {
        const int buf = kc & 1;
        if (kc < 11) {
            loadA(kc + 1);
            issueB(kc + 1, buf ^ 1);
            cp_wait<1>();
        } else {
            cp_wait<0>();
        }
        __syncthreads();

        const __half* aS = sh + buf * A_STAGE;
        const __half* bS = sh + B_BASE + buf * B_STAGE;

        #pragma unroll
        for (int ks = 0; ks < 2; ++ks) {
            wmma::fragment<wmma::matrix_a, 16, 16, 16, __half, wmma::row_major> a[2];
            wmma::fragment<wmma::matrix_b, 16, 16, 16, __half, wmma::row_major> b[4];
            #pragma unroll
            for (int i = 0; i < 2; ++i)
                wmma::load_matrix_sync(a[i], aS + (wym * 32 + i * 16) * AST + ks * 16, AST);
            #pragma unroll
            for (int j = 0; j < 4; ++j)
                wmma::load_matrix_sync(b[j], bS + (ks * 16) * BST + wxn * 64 + j * 16, BST);
            #pragma unroll
            for (int i = 0; i < 2; ++i)
                #pragma unroll
                for (int j = 0; j < 4; ++j)
                    wmma::mma_sync(acc[i][j], a[i], b[j], acc[i][j]);
        }
        __syncthreads();
        if (kc < 11) storeA(buf ^ 1);
    }

    float* dst = (wxn == 0) ? g_q : (wxn == 1) ? g_k : g_v;
    #pragma unroll
    for (int i = 0; i < 2; ++i) {
        size_t row = rowBase + wym * 32 + i * 16;
        #pragma unroll
        for (int j = 0; j < 4; ++j)
            wmma::store_matrix_sync(dst + row * HS + j * 16, acc[i][j], HS,
                                    wmma::mem_row_major);
    }
}

// ---------------------------------------------------------------------------
// Kernel 2: causal flash attention on raw mma.sync (split-fp16 3-term).
// CTA: 128 q rows x key loop. 8 warps, warp w: rows w*16..+15, all 64 HS cols.
// Online softmax in registers (C-frag layout == A-frag layout trick).
// smem: K/V tile hi/lo, stride 72 halfs (144B -> conflict-free ldmatrix).
// ---------------------------------------------------------------------------
#define KST 72

__global__ __launch_bounds__(256) void attn_mma(float* __restrict__ out)
{
    __shared__ __align__(16) __half s_kh[64 * KST];
    __shared__ __align__(16) __half s_kl[64 * KST];
    __shared__ __align__(16) __half s_vh[64 * KST];
    __shared__ __align__(16) __half s_vl[64 * KST];

    const int tid  = threadIdx.x;
    const int lane = tid & 31;
    const int w    = tid >> 5;
    const int b    = blockIdx.y;
    const int qt2  = blockIdx.x;               // 0..1 (128-row q block)
    const int nt   = qt2 * 2 + 2;              // key tiles to process
    const size_t qrow0 = (size_t)b * BT + qt2 * 128;
    const float scale = 0.05103103630798288f;  // 384^-0.5

    // --- stage Q (fp32 -> fp16 hi/lo) into the 4 smem buffers ---
    #pragma unroll
    for (int p = 0; p < 8; ++p) {
        int i  = tid + p * 256;                // 2048 float4 = 128x64
        int r  = i >> 4;
        int c4 = i & 15;
        float4 v = *(const float4*)(g_q + (qrow0 + r) * HS + c4 * 4);
        float hx = __half2float(__float2half_rn(v.x));
        float hy = __half2float(__float2half_rn(v.y));
        float hz = __half2float(__float2half_rn(v.z));
        float hw = __half2float(__float2half_rn(v.w));
        __half* dh = ((r < 64) ? s_kh : s_vh) + (r & 63) * KST + c4 * 4;
        __half* dl = ((r < 64) ? s_kl : s_vl) + (r & 63) * KST + c4 * 4;
        ((__half2*)dh)[0] = __floats2half2_rn(v.x, v.y);
        ((__half2*)dh)[1] = __floats2half2_rn(v.z, v.w);
        ((__half2*)dl)[0] = __floats2half2_rn(v.x - hx, v.y - hy);
        ((__half2*)dl)[1] = __floats2half2_rn(v.z - hz, v.w - hw);
    }
    __syncthreads();

    // --- Q fragments (held in registers across the whole key loop) ---
    uint32_t qh[4][4], ql[4][4];
    const int wrow = w * 16;
    {
        int sub = lane >> 3, r8 = lane & 7;
        int rloc = wrow + (sub & 1) * 8 + r8;
        const __half* bh_ = (rloc < 64) ? s_kh : s_vh;
        const __half* bl_ = (rloc < 64) ? s_kl : s_vl;
        uint32_t ah_ = smem_u32(bh_ + (rloc & 63) * KST) + (sub >> 1) * 16;
        uint32_t al_ = smem_u32(bl_ + (rloc & 63) * KST) + (sub >> 1) * 16;
        #pragma unroll
        for (int kk = 0; kk < 4; ++kk) {
            ldsm_x4(qh[kk], ah_ + kk * 32);
            ldsm_x4(ql[kk], al_ + kk * 32);
        }
    }

    float o[8][4];
    #pragma unroll
    for (int t = 0; t < 8; ++t)
        #pragma unroll
        for (int i = 0; i < 4; ++i) o[t][i] = 0.0f;
    float m_lo = -1e30f, m_hi = -1e30f, l_lo = 0.0f, l_hi = 0.0f;

    const int growmin = qt2 * 128 + wrow;
    const int growmax = growmin + 15;
    const int grow_lo = growmin + (lane >> 2);
    const int grow_hi = grow_lo + 8;

    for (int st = 0; st < nt; ++st) {
        __syncthreads();   // prior compute done; buffers reusable
        // --- load K,V tile (fp32 -> fp16 hi/lo) ---
        #pragma unroll
        for (int p = 0; p < 4; ++p) {
            int i  = tid + p * 256;            // 1024 float4 = 64x64
            int r  = i >> 4;
            int c4 = i & 15;
            size_t src = ((size_t)b * BT + st * 64 + r) * HS + c4 * 4;
            float4 kv = *(const float4*)(g_k + src);
            float4 vv = *(const float4*)(g_v + src);
            {
                float hx = __half2float(__float2half_rn(kv.x));
                float hy = __half2float(__float2half_rn(kv.y));
                float hz = __half2float(__float2half_rn(kv.z));
                float hw = __half2float(__float2half_rn(kv.w));
                __half* dh = s_kh + r * KST + c4 * 4;
                __half* dl = s_kl + r * KST + c4 * 4;
                ((__half2*)dh)[0] = __floats2half2_rn(kv.x, kv.y);
                ((__half2*)dh)[1] = __floats2half2_rn(kv.z, kv.w);
                ((__half2*)dl)[0] = __floats2half2_rn(kv.x - hx, kv.y - hy);
                ((__half2*)dl)[1] = __floats2half2_rn(kv.z - hz, kv.w - hw);
            }
            {
                float hx = __half2float(__float2half_rn(vv.x));
                float hy = __half2float(__float2half_rn(vv.y));
                float hz = __half2float(__float2half_rn(vv.z));
                float hw = __half2float(__float2half_rn(vv.w));
                __half* dh = s_vh + r * KST + c4 * 4;
                __half* dl = s_vl + r * KST + c4 * 4;
                ((__half2*)dh)[0] = __floats2half2_rn(vv.x, vv.y);
                ((__half2*)dh)[1] = __floats2half2_rn(vv.z, vv.w);
                ((__half2*)dl)[0] = __floats2half2_rn(vv.x - hx, vv.y - hy);
                ((__half2*)dl)[1] = __floats2half2_rn(vv.z - hz, vv.w - hw);
            }
        }
        __syncthreads();   // data ready

        if (st * 64 > growmax) continue;   // fully-masked tile for this warp

        // --- S = Q K^T (3-term split), c[t] = n8-tile t accumulators ---
        float c[8][4];
        #pragma unroll
        for (int t = 0; t < 8; ++t)
            #pragma unroll
            for (int i = 0; i < 4; ++i) c[t][i] = 0.0f;

        {
            int sub = lane >> 3, r8 = lane & 7;
            #pragma unroll
            for (int kk = 0; kk < 4; ++kk) {
                #pragma unroll
                for (int tp = 0; tp < 4; ++tp) {
                    int krow = (2 * tp + (sub >> 1)) * 8 + r8;
                    uint32_t off = kk * 32 + (sub & 1) * 16;
                    uint32_t bh4[4], bl4[4];
                    ldsm_x4(bh4, smem_u32(s_kh + krow * KST) + off);
                    ldsm_x4(bl4, smem_u32(s_kl + krow * KST) + off);
                    #pragma unroll
                    for (int tt = 0; tt < 2; ++tt) {
                        int t = 2 * tp + tt;
                        mma16816(c[t], qh[kk], &bh4[2 * tt]);
                        mma16816(c[t], qh[kk], &bl4[2 * tt]);
                        mma16816(c[t], ql[kk], &bh4[2 * tt]);
                    }
                }
            }
        }

        // --- scale + causal mask ---
        #pragma unroll
        for (int t = 0; t < 8; ++t)
            #pragma unroll
            for (int i = 0; i < 4; ++i) c[t][i] *= scale;

        if (st * 64 + 63 > growmin) {      // boundary tile for this warp
            int colb = st * 64 + 2 * (lane & 3);
            #pragma unroll
            for (int t = 0; t < 8; ++t) {
                int c0 = colb + 8 * t, c1 = c0 + 1;
                if (c0 > grow_lo) c[t][0] = -1e30f;
                if (c1 > grow_lo) c[t][1] = -1e30f;
                if (c0 > grow_hi) c[t][2] = -1e30f;
                if (c1 > grow_hi) c[t][3] = -1e30f;
            }
        }

        // --- online softmax in registers (4 lanes per row) ---
        float mx0 = -1e30f, mx1 = -1e30f;
        #pragma unroll
        for (int t = 0; t < 8; ++t) {
            mx0 = fmaxf(mx0, fmaxf(c[t][0], c[t][1]));
            mx1 = fmaxf(mx1, fmaxf(c[t][2], c[t][3]));
        }
        mx0 = fmaxf(mx0, __shfl_xor_sync(0xffffffffu, mx0, 1, 4));
        mx0 = fmaxf(mx0, __shfl_xor_sync(0xffffffffu, mx0, 2, 4));
        mx1 = fmaxf(mx1, __shfl_xor_sync(0xffffffffu, mx1, 1, 4));
        mx1 = fmaxf(mx1, __shfl_xor_sync(0xffffffffu, mx1, 2, 4));
        float mn0 = fmaxf(m_lo, mx0), mn1 = fmaxf(m_hi, mx1);
        float al0 = fast_exp(m_lo - mn0), al1 = fast_exp(m_hi - mn1);
        m_lo = mn0; m_hi = mn1;

        float s0 = 0.0f, s1 = 0.0f;
        #pragma unroll
        for (int t = 0; t < 8; ++t) {
            c[t][0] = fast_exp(c[t][0] - mn0); s0 += c[t][0];
            c[t][1] = fast_exp(c[t][1] - mn0); s0 += c[t][1];
            c[t][2] = fast_exp(c[t][2] - mn1); s1 += c[t][2];
            c[t][3] = fast_exp(c[t][3] - mn1); s1 += c[t][3];
        }
        s0 += __shfl_xor_sync(0xffffffffu, s0, 1, 4);
        s0 += __shfl_xor_sync(0xffffffffu, s0, 2, 4);
        s1 += __shfl_xor_sync(0xffffffffu, s1, 1, 4);
        s1 += __shfl_xor_sync(0xffffffffu, s1, 2, 4);
        l_lo = l_lo * al0 + s0;
        l_hi = l_hi * al1 + s1;
        #pragma unroll
        for (int t = 0; t < 8; ++t) {
            o[t][0] *= al0; o[t][1] *= al0;
            o[t][2] *= al1; o[t][3] *= al1;
        }

        // --- O += P V (3-term: Ph*Vh + Ph*Vl + Pl*Vh) ---
        {
            int sub = lane >> 3, r8 = lane & 7;
            #pragma unroll
            for (int kv = 0; kv < 4; ++kv) {
                // P a-frags from c regs (C layout == A layout)
                uint32_t ah[4], alr[4];
                #pragma unroll
                for (int half = 0; half < 2; ++half) {   // k 0-7 / 8-15
                    int tt = 2 * kv + half;
                    __half h0 = __float2half_rn(c[tt][0]);
                    __half h1 = __float2half_rn(c[tt][1]);
                    __half h2 = __float2half_rn(c[tt][2]);
                    __half h3 = __float2half_rn(c[tt][3]);
                    ah[half * 2 + 0] = pack_h2(h0, h1);
                    ah[half * 2 + 1] = pack_h2(h2, h3);
                    alr[half * 2 + 0] = pack_h2(
                        __float2half_rn(c[tt][0] - __half2float(h0)),
                        __float2half_rn(c[tt][1] - __half2float(h1)));
                    alr[half * 2 + 1] = pack_h2(
                        __float2half_rn(c[tt][2] - __half2float(h2)),
                        __float2half_rn(c[tt][3] - __half2float(h3)));
                }
                // note: a-frag reg order is {k0-7 row, k0-7 row+8, k8-15 row, k8-15 row+8}
                uint32_t af_h[4] = {ah[0], ah[1], ah[2], ah[3]};
                uint32_t af_l[4] = {alr[0], alr[1], alr[2], alr[3]};

                int vrow = kv * 16 + (sub & 1) * 8 + r8;
                #pragma unroll
                for (int tp = 0; tp < 4; ++tp) {
                    uint32_t off = 16 * (2 * tp + (sub >> 1));
                    uint32_t vh4[4], vl4[4];
                    ldsm_x4_t(vh4, smem_u32(s_vh + vrow * KST) + off);
                    ldsm_x4_t(vl4, smem_u32(s_vl + vrow * KST) + off);
                    #pragma unroll
                    for (int tt = 0; tt < 2; ++tt) {
                        int t = 2 * tp + tt;
                        mma16816(o[t], af_h, &vh4[2 * tt]);
                        mma16816(o[t], af_h, &vl4[2 * tt]);
                        mma16816(o[t], af_l, &vh4[2 * tt]);
                    }
                }
            }
        }
    }

    // --- epilogue: normalize by 1/l, write out ---
    float inv0 = 1.0f / l_lo, inv1 = 1.0f / l_hi;
    int rlo = wrow + (lane >> 2);
    size_t base_lo = (qrow0 + rlo) * HS + 2 * (lane & 3);
    size_t base_hi = (qrow0 + rlo + 8) * HS + 2 * (lane & 3);
    #pragma unroll
    for (int t = 0; t < 8; ++t) {
        *(float2*)(out + base_lo + 8 * t) = make_float2(o[t][0] * inv0, o[t][1] * inv0);
        *(float2*)(out + base_hi + 8 * t) = make_float2(o[t][2] * inv1, o[t][3] * inv1);
    }
}

// ---------------------------------------------------------------------------
// Launch
// ---------------------------------------------------------------------------
extern "C" void kernel_launch(void* const* d_in, const int* in_sizes, int n_in,
                              void* d_out, int out_size)
{
    (void)in_sizes; (void)n_in; (void)out_size;
    const float* x  = (const float*)d_in[0];
    const float* Wq = (const float*)d_in[1];
    const float* Wk = (const float*)d_in[2];
    const float* Wv = (const float*)d_in[3];
    float* out = (float*)d_out;

    cudaFuncSetAttribute(qkv_proj_wmma,
                         cudaFuncAttributeMaxDynamicSharedMemorySize,
                         P_SMEM_BYTES);

    // W -> combined fp16
    wconv_kernel<<<(3 * CE * HS + 255) / 256, 256>>>(Wq, Wk, Wv);

    // QKV projection on tensor cores: 262144 rows / 128 per CTA = 2048 CTAs
    qkv_proj_wmma<<<2048, 384, P_SMEM_BYTES>>>(x);

    // Attention: 2 q-blocks of 128 rows x 1024 batches
    attn_mma<<<dim3(2, NB), 256>>>(out);
}